// round 6
// baseline (speedup 1.0000x reference)
#include <cuda_runtime.h>
#include <math.h>

// ---------------- problem constants ----------------
#define D_DIM 2048
#define M_DIM 7168
#define E_NUM 8
#define T_TOK 4096            // B*S
#define TR    (T_TOK * 2)     // top-2 replicas

#define BM 64
#define BN 64
#define BK 16
#define CHUNK_M 1024                    // M processed in 7 chunks
#define N_CHUNKS (M_DIM / CHUNK_M)      // 7
#define MAX_TILES 160
#define MAX_RT    136                   // max row tiles = 8192/64 + 8
#define MAX_ROWS  (TR + E_NUM * BM)     // 8704 padded permuted rows

// ---------------- static device scratch (no allocs allowed) ----------------
__device__ float g_hc[(size_t)MAX_ROWS * CHUNK_M];  // gated hidden, one M-chunk (35.7 MB)
__device__ float g_outrep[(size_t)TR * D_DIM];      // per-replica expert output (67 MB)
__device__ int   g_row_map[MAX_ROWS];               // permuted row -> source token (or -1 pad)
__device__ int   g_repl_map[MAX_ROWS];              // permuted row -> replica id (or -1 pad)
__device__ int   g_eidx[TR];                        // replica -> expert
__device__ float g_tw[TR];                          // replica -> combine weight
__device__ int   g_tile_e[MAX_TILES];
__device__ int   g_tile_row[MAX_TILES];
__device__ int   g_ntiles;

// ---------------- init ----------------
__global__ void k_init() {
    for (int i = threadIdx.x; i < MAX_ROWS; i += blockDim.x) {
        g_row_map[i]  = -1;
        g_repl_map[i] = -1;
    }
}

// ---------------- router: one warp per token ----------------
__global__ void k_router(const float* __restrict__ x, const float* __restrict__ gw) {
    int warp = (blockIdx.x * blockDim.x + threadIdx.x) >> 5;
    int lane = threadIdx.x & 31;
    if (warp >= T_TOK) return;
    const float* xr = x + (size_t)warp * D_DIM;

    float acc[8] = {0.f,0.f,0.f,0.f,0.f,0.f,0.f,0.f};
    for (int k = lane; k < D_DIM; k += 32) {
        float xv = xr[k];
        const float4* g4 = (const float4*)(gw + (size_t)k * E_NUM);
        float4 g0 = g4[0];
        float4 g1 = g4[1];
        acc[0] += xv * g0.x; acc[1] += xv * g0.y;
        acc[2] += xv * g0.z; acc[3] += xv * g0.w;
        acc[4] += xv * g1.x; acc[5] += xv * g1.y;
        acc[6] += xv * g1.z; acc[7] += xv * g1.w;
    }
#pragma unroll
    for (int e = 0; e < 8; e++) {
#pragma unroll
        for (int o = 16; o > 0; o >>= 1)
            acc[e] += __shfl_xor_sync(0xFFFFFFFFu, acc[e], o);
    }
    if (lane == 0) {
        int e0 = 0; float l0 = acc[0];
#pragma unroll
        for (int e = 1; e < 8; e++)
            if (acc[e] > l0) { l0 = acc[e]; e0 = e; }
        int e1 = -1; float l1 = -3.4e38f;
#pragma unroll
        for (int e = 0; e < 8; e++)
            if (e != e0 && acc[e] > l1) { l1 = acc[e]; e1 = e; }
        // normalized pair weights from softmax over the two logits
        float w0 = 1.f / (1.f + __expf(l1 - l0));
        float w1 = 1.f - w0;
        g_eidx[2 * warp]     = e0;
        g_eidx[2 * warp + 1] = e1;
        g_tw[2 * warp]       = w0;
        g_tw[2 * warp + 1]   = w1;
    }
}

// ---------------- permutation + tile list (single block) ----------------
__global__ void k_perm() {
    __shared__ int sc[E_NUM];
    __shared__ int soff[E_NUM];
    __shared__ int scur[E_NUM];
    int t = threadIdx.x;
    if (t < E_NUM) { sc[t] = 0; scur[t] = 0; }
    __syncthreads();
    for (int r = t; r < TR; r += blockDim.x)
        atomicAdd(&sc[g_eidx[r]], 1);
    __syncthreads();
    if (t == 0) {
        int off = 0, nt = 0;
        for (int e = 0; e < E_NUM; e++) {
            soff[e] = off;
            int cnt = sc[e];
            for (int t0 = 0; t0 < cnt; t0 += BM) {
                g_tile_e[nt]   = e;
                g_tile_row[nt] = off + t0;
                nt++;
            }
            off += ((cnt + BM - 1) / BM) * BM;
        }
        g_ntiles = nt;
    }
    __syncthreads();
    for (int r = t; r < TR; r += blockDim.x) {
        int e   = g_eidx[r];
        int pos = soff[e] + atomicAdd(&scur[e], 1);
        g_row_map[pos]  = r >> 1;   // token
        g_repl_map[pos] = r;        // replica
    }
}

// -------- GEMM1 (chunked): g_hc = silu(X@W1[:,c0:c0+CHUNK]) * (X@W3[:,c0:...]) --------
__global__ void __launch_bounds__(256)
k_gemm1(const float* __restrict__ x,
        const float* __restrict__ w1,
        const float* __restrict__ w3,
        int c0) {
    int bx = blockIdx.x;
    if (bx >= g_ntiles) return;
    int e  = g_tile_e[bx];
    int r0 = g_tile_row[bx];
    int nl = blockIdx.y * BN;        // local column within chunk
    int n0 = c0 + nl;                // global column in W1/W3

    const float* W1 = w1 + (size_t)e * D_DIM * M_DIM;
    const float* W3 = w3 + (size_t)e * D_DIM * M_DIM;

    __shared__ float As[BK][BM];
    __shared__ float B1s[BK][BN];
    __shared__ float B3s[BK][BN];

    int tid = threadIdx.x;
    int tx = tid & 15, ty = tid >> 4;

    int arow = tid >> 2;            // 0..63
    int ak   = (tid & 3) * 4;       // 0,4,8,12
    int brow = tid >> 4;            // 0..15
    int bj   = (tid & 15) * 4;      // 0..60

    int grow = g_row_map[r0 + arow];
    const float* ap = (grow >= 0) ? (x + (size_t)grow * D_DIM) : x;

    float acc1[4][4] = {{0}}, acc3[4][4] = {{0}};

    // prologue: prefetch tile 0 into registers
    float4 av = make_float4(0.f, 0.f, 0.f, 0.f);
    if (grow >= 0) av = *(const float4*)(ap + ak);
    float4 b1v = *(const float4*)(W1 + (size_t)brow * M_DIM + n0 + bj);
    float4 b3v = *(const float4*)(W3 + (size_t)brow * M_DIM + n0 + bj);

    for (int k0 = 0; k0 < D_DIM; k0 += BK) {
        As[ak + 0][arow] = av.x;
        As[ak + 1][arow] = av.y;
        As[ak + 2][arow] = av.z;
        As[ak + 3][arow] = av.w;
        *(float4*)&B1s[brow][bj] = b1v;
        *(float4*)&B3s[brow][bj] = b3v;
        __syncthreads();

        int k1 = k0 + BK;
        if (k1 < D_DIM) {
            av = make_float4(0.f, 0.f, 0.f, 0.f);
            if (grow >= 0) av = *(const float4*)(ap + k1 + ak);
            b1v = *(const float4*)(W1 + (size_t)(k1 + brow) * M_DIM + n0 + bj);
            b3v = *(const float4*)(W3 + (size_t)(k1 + brow) * M_DIM + n0 + bj);
        }

#pragma unroll
        for (int kk = 0; kk < BK; kk++) {
            float4 a  = *(const float4*)&As[kk][ty * 4];
            float4 b1 = *(const float4*)&B1s[kk][tx * 4];
            float4 b3 = *(const float4*)&B3s[kk][tx * 4];
            float aa[4]  = {a.x, a.y, a.z, a.w};
            float bb1[4] = {b1.x, b1.y, b1.z, b1.w};
            float bb3[4] = {b3.x, b3.y, b3.z, b3.w};
#pragma unroll
            for (int i = 0; i < 4; i++)
#pragma unroll
                for (int j = 0; j < 4; j++) {
                    acc1[i][j] += aa[i] * bb1[j];
                    acc3[i][j] += aa[i] * bb3[j];
                }
        }
        __syncthreads();
    }

#pragma unroll
    for (int i = 0; i < 4; i++) {
        int row = r0 + ty * 4 + i;
        if (g_row_map[row] < 0) continue;
        float* hp = g_hc + (size_t)row * CHUNK_M + nl + tx * 4;
        float4 o;
        float v;
        v = acc1[i][0]; o.x = (v / (1.f + __expf(-v))) * acc3[i][0];
        v = acc1[i][1]; o.y = (v / (1.f + __expf(-v))) * acc3[i][1];
        v = acc1[i][2]; o.z = (v / (1.f + __expf(-v))) * acc3[i][2];
        v = acc1[i][3]; o.w = (v / (1.f + __expf(-v))) * acc3[i][3];
        *(float4*)hp = o;
    }
}

// -------- GEMM2 (chunked): out_rep (+)= g_hc @ W2[c0:c0+CHUNK, :], scatter by replica ----
__global__ void __launch_bounds__(256)
k_gemm2(const float* __restrict__ w2, int c0, int first) {
    int bx = blockIdx.x;
    if (bx >= g_ntiles) return;
    int e  = g_tile_e[bx];
    int r0 = g_tile_row[bx];
    int n0 = blockIdx.y * BN;

    const float* W2 = w2 + (size_t)e * M_DIM * D_DIM + (size_t)c0 * D_DIM;

    __shared__ float As[BK][BM];
    __shared__ float Bs[BK][BN];

    int tid = threadIdx.x;
    int tx = tid & 15, ty = tid >> 4;

    int arow = tid >> 2;
    int ak   = (tid & 3) * 4;
    int brow = tid >> 4;
    int bj   = (tid & 15) * 4;

    const float* ap = g_hc + (size_t)(r0 + arow) * CHUNK_M;

    float acc[4][4] = {{0}};

    // prologue: prefetch tile 0
    float4 av = *(const float4*)(ap + ak);
    float4 bv = *(const float4*)(W2 + (size_t)brow * D_DIM + n0 + bj);

    for (int k0 = 0; k0 < CHUNK_M; k0 += BK) {
        As[ak + 0][arow] = av.x;
        As[ak + 1][arow] = av.y;
        As[ak + 2][arow] = av.z;
        As[ak + 3][arow] = av.w;
        *(float4*)&Bs[brow][bj] = bv;
        __syncthreads();

        int k1 = k0 + BK;
        if (k1 < CHUNK_M) {
            av = *(const float4*)(ap + k1 + ak);
            bv = *(const float4*)(W2 + (size_t)(k1 + brow) * D_DIM + n0 + bj);
        }

#pragma unroll
        for (int kk = 0; kk < BK; kk++) {
            float4 a = *(const float4*)&As[kk][ty * 4];
            float4 b = *(const float4*)&Bs[kk][tx * 4];
            float aa[4] = {a.x, a.y, a.z, a.w};
            float bb[4] = {b.x, b.y, b.z, b.w};
#pragma unroll
            for (int i = 0; i < 4; i++)
#pragma unroll
                for (int j = 0; j < 4; j++)
                    acc[i][j] += aa[i] * bb[j];
        }
        __syncthreads();
    }

#pragma unroll
    for (int i = 0; i < 4; i++) {
        int row = r0 + ty * 4 + i;
        int rr  = g_repl_map[row];
        if (rr < 0) continue;
        float* op = g_outrep + (size_t)rr * D_DIM + n0 + tx * 4;
        float4 o = make_float4(acc[i][0], acc[i][1], acc[i][2], acc[i][3]);
        if (!first) {
            float4 p = *(const float4*)op;
            o.x += p.x; o.y += p.y; o.z += p.z; o.w += p.w;
        }
        *(float4*)op = o;
    }
}

// ---------------- combine: out[t] = w0*rep[2t] + w1*rep[2t+1] ----------------
__global__ void k_combine(float* __restrict__ out) {
    int i = blockIdx.x * blockDim.x + threadIdx.x;   // float4 index
    int t = i >> 9;                                  // 512 float4 per row
    int c = (i & 511) * 4;
    if (t >= T_TOK) return;
    float w0 = g_tw[2 * t];
    float w1 = g_tw[2 * t + 1];
    float4 a = *(const float4*)&g_outrep[(size_t)(2 * t) * D_DIM + c];
    float4 b = *(const float4*)&g_outrep[(size_t)(2 * t + 1) * D_DIM + c];
    float4 o;
    o.x = w0 * a.x + w1 * b.x;
    o.y = w0 * a.y + w1 * b.y;
    o.z = w0 * a.z + w1 * b.z;
    o.w = w0 * a.w + w1 * b.w;
    *(float4*)&out[(size_t)t * D_DIM + c] = o;
}

// ---------------- launch ----------------
extern "C" void kernel_launch(void* const* d_in, const int* in_sizes, int n_in,
                              void* d_out, int out_size) {
    const float* x  = (const float*)d_in[0];
    const float* gw = (const float*)d_in[1];
    const float* w1 = (const float*)d_in[2];
    const float* w2 = (const float*)d_in[3];
    const float* w3 = (const float*)d_in[4];
    float* out = (float*)d_out;

    k_init<<<1, 256>>>();
    k_router<<<T_TOK / 8, 256>>>(x, gw);
    k_perm<<<1, 256>>>();
    for (int c = 0; c < N_CHUNKS; c++) {
        int c0 = c * CHUNK_M;
        k_gemm1<<<dim3(MAX_RT, CHUNK_M / BN), 256>>>(x, w1, w3, c0);
        k_gemm2<<<dim3(MAX_RT, D_DIM / BN), 256>>>(w2, c0, c == 0);
    }
    k_combine<<<(T_TOK * D_DIM / 4) / 256, 256>>>(out);
}

// round 9
// speedup vs baseline: 1.4406x; 1.4406x over previous
#include <cuda_runtime.h>
#include <cuda_bf16.h>
#include <stdint.h>
#include <math.h>

// ---------------- problem constants ----------------
#define D_DIM 2048
#define M_DIM 7168
#define E_NUM 8
#define T_TOK 4096
#define TR    (T_TOK * 2)

#define TILE_M 128                          // row-tile granularity (BM)
#define CHUNK_M 1792
#define N_CHUNKS (M_DIM / CHUNK_M)          // 4
#define PADROWS  (TR + E_NUM * TILE_M)      // 9216
#define MAX_RT   80                         // tile list capacity (worst case 72)

#define BK 32                               // K elements per stage
#define PITCH 72                            // smem row pitch bytes (36 bf16)

// per-stage smem layout (bytes)
#define STG_BYTES 36864
// gemm1: AH 0, AL 9216, B1H 18432, B1L 23040, B3H 27648, B3L 32256
// gemm2: AH 0, AL 9216, BH 18432, BL 27648
#define OFF_AH 0
#define OFF_AL 9216
#define G1_B1H 18432
#define G1_B1L 23040
#define G1_B3H 27648
#define G1_B3L 32256
#define G2_BH  18432
#define G2_BL  27648
#define SMEM_TOTAL (2 * STG_BYTES)          // 73728

// ---------------- static device scratch ----------------
__device__ float g_hc[(size_t)PADROWS * CHUNK_M];   // hidden chunk, row-major, 66 MB
__device__ float g_outrep[(size_t)TR * D_DIM];      // per-replica output, 67 MB
__device__ int   g_row_map[PADROWS];
__device__ int   g_repl_map[PADROWS];
__device__ int   g_eidx[TR];
__device__ float g_tw[TR];
__device__ int   g_tile_e[MAX_RT];
__device__ int   g_tile_row[MAX_RT];
__device__ int   g_ntiles;

// ---------------- helpers ----------------
__device__ __forceinline__ uint32_t phi(float a, float b) {
    __nv_bfloat162 t = __floats2bfloat162_rn(a, b);
    return *reinterpret_cast<uint32_t*>(&t);
}
__device__ __forceinline__ uint32_t plo(float a, float b) {
    float ah = __bfloat162float(__float2bfloat16_rn(a));
    float bh = __bfloat162float(__float2bfloat16_rn(b));
    return phi(a - ah, b - bh);
}
__device__ __forceinline__ void mma16816(float* c, const uint32_t* a, const uint32_t* b) {
    asm volatile(
        "mma.sync.aligned.m16n8k16.row.col.f32.bf16.bf16.f32 "
        "{%0,%1,%2,%3}, {%4,%5,%6,%7}, {%8,%9}, {%0,%1,%2,%3};"
        : "+f"(c[0]), "+f"(c[1]), "+f"(c[2]), "+f"(c[3])
        : "r"(a[0]), "r"(a[1]), "r"(a[2]), "r"(a[3]), "r"(b[0]), "r"(b[1]));
}
__device__ __forceinline__ uint32_t lds32(const char* p) {
    return *reinterpret_cast<const uint32_t*>(p);
}
__device__ __forceinline__ float silu(float v) {
    return v / (1.f + __expf(-v));
}

// ---------------- init ----------------
__global__ void k_init() {
    for (int i = threadIdx.x; i < PADROWS; i += blockDim.x) {
        g_row_map[i]  = -1;
        g_repl_map[i] = -1;
    }
}

// ---------------- router: one warp per token ----------------
__global__ void k_router(const float* __restrict__ x, const float* __restrict__ gw) {
    int warp = (blockIdx.x * blockDim.x + threadIdx.x) >> 5;
    int lane = threadIdx.x & 31;
    if (warp >= T_TOK) return;
    const float* xr = x + (size_t)warp * D_DIM;
    float acc[8] = {0.f,0.f,0.f,0.f,0.f,0.f,0.f,0.f};
    for (int k = lane; k < D_DIM; k += 32) {
        float xv = xr[k];
        const float4* g4 = (const float4*)(gw + (size_t)k * E_NUM);
        float4 g0 = g4[0], g1 = g4[1];
        acc[0] += xv * g0.x; acc[1] += xv * g0.y; acc[2] += xv * g0.z; acc[3] += xv * g0.w;
        acc[4] += xv * g1.x; acc[5] += xv * g1.y; acc[6] += xv * g1.z; acc[7] += xv * g1.w;
    }
#pragma unroll
    for (int e = 0; e < 8; e++)
#pragma unroll
        for (int o = 16; o > 0; o >>= 1)
            acc[e] += __shfl_xor_sync(0xFFFFFFFFu, acc[e], o);
    if (lane == 0) {
        int e0 = 0; float l0 = acc[0];
#pragma unroll
        for (int e = 1; e < 8; e++) if (acc[e] > l0) { l0 = acc[e]; e0 = e; }
        int e1 = -1; float l1 = -3.4e38f;
#pragma unroll
        for (int e = 0; e < 8; e++) if (e != e0 && acc[e] > l1) { l1 = acc[e]; e1 = e; }
        float w0 = 1.f / (1.f + __expf(l1 - l0));
        g_eidx[2 * warp] = e0; g_eidx[2 * warp + 1] = e1;
        g_tw[2 * warp] = w0;   g_tw[2 * warp + 1] = 1.f - w0;
    }
}

// ---------------- permutation + tile list ----------------
__global__ void k_perm() {
    __shared__ int sc[E_NUM], soff[E_NUM], scur[E_NUM];
    int t = threadIdx.x;
    if (t < E_NUM) { sc[t] = 0; scur[t] = 0; }
    __syncthreads();
    for (int r = t; r < TR; r += blockDim.x) atomicAdd(&sc[g_eidx[r]], 1);
    __syncthreads();
    if (t == 0) {
        int off = 0, nt = 0;
        for (int e = 0; e < E_NUM; e++) {
            soff[e] = off;
            int cnt = sc[e];
            for (int t0 = 0; t0 < cnt; t0 += TILE_M) {
                g_tile_e[nt] = e; g_tile_row[nt] = off + t0; nt++;
            }
            off += ((cnt + TILE_M - 1) / TILE_M) * TILE_M;
        }
        g_ntiles = nt;
    }
    __syncthreads();
    for (int r = t; r < TR; r += blockDim.x) {
        int e = g_eidx[r];
        int pos = soff[e] + atomicAdd(&scur[e], 1);
        g_row_map[pos]  = r >> 1;
        g_repl_map[pos] = r;
    }
}

// ============ GEMM1: h = silu(X@W1_chunk) * (X@W3_chunk), tensor cores ============
__global__ void __launch_bounds__(256)
k_gemm1(const float* __restrict__ x,
        const float* __restrict__ w1,
        const float* __restrict__ w3, int c0) {
    extern __shared__ char smem[];
    int bx = blockIdx.x;
    if (bx >= g_ntiles) return;
    int e  = g_tile_e[bx];
    int r0 = g_tile_row[bx];
    int nl = blockIdx.y * 64;               // chunk-local col

    const float* W1 = w1 + (size_t)e * D_DIM * M_DIM + c0 + nl;
    const float* W3 = w3 + (size_t)e * D_DIM * M_DIM + c0 + nl;

    int tid = threadIdx.x;
    int w = tid >> 5, lane = tid & 31, g = lane >> 2, q = lane & 3;
    int m0 = (w & 3) * 32, n0w = (w >> 2) * 32;

    // staging indices
    int k4 = tid & 7, mrow = tid >> 3;      // A: float4 at k4, rows mrow+32i
    int bn = tid & 63, bg = tid >> 6;       // B: col bn, k-pair group bg (0..3)

    const float* aptr[4];
#pragma unroll
    for (int i = 0; i < 4; i++) {
        int gr = g_row_map[r0 + mrow + 32 * i];
        aptr[i] = (gr >= 0) ? x + (size_t)gr * D_DIM : (const float*)0;
    }

    char* buf[2] = { smem, smem + STG_BYTES };
    float c1[2][4][4] = {{{0}}}, c3[2][4][4] = {{{0}}};

    float4 va[4]; float2 vb1[4], vb3[4];
    // prologue: stage 0
#pragma unroll
    for (int i = 0; i < 4; i++)
        va[i] = aptr[i] ? *(const float4*)(aptr[i] + k4 * 4) : make_float4(0.f,0.f,0.f,0.f);
#pragma unroll
    for (int j = 0; j < 4; j++) {
        int kk = (bg * 4 + j) * 2;
        vb1[j] = make_float2(W1[(size_t)kk * M_DIM + bn], W1[(size_t)(kk + 1) * M_DIM + bn]);
        vb3[j] = make_float2(W3[(size_t)kk * M_DIM + bn], W3[(size_t)(kk + 1) * M_DIM + bn]);
    }
    {
        char* s = buf[0];
        uint32_t ab = (uint32_t)mrow * PITCH + k4 * 8;
#pragma unroll
        for (int i = 0; i < 4; i++) {
            uint32_t o = ab + i * 32 * PITCH;
            *(uint32_t*)(s + OFF_AH + o)     = phi(va[i].x, va[i].y);
            *(uint32_t*)(s + OFF_AH + o + 4) = phi(va[i].z, va[i].w);
            *(uint32_t*)(s + OFF_AL + o)     = plo(va[i].x, va[i].y);
            *(uint32_t*)(s + OFF_AL + o + 4) = plo(va[i].z, va[i].w);
        }
#pragma unroll
        for (int j = 0; j < 4; j++) {
            int kp = bg * 4 + j;
            uint32_t o = (uint32_t)bn * PITCH + kp * 4;
            *(uint32_t*)(s + G1_B1H + o) = phi(vb1[j].x, vb1[j].y);
            *(uint32_t*)(s + G1_B1L + o) = plo(vb1[j].x, vb1[j].y);
            *(uint32_t*)(s + G1_B3H + o) = phi(vb3[j].x, vb3[j].y);
            *(uint32_t*)(s + G1_B3L + o) = plo(vb3[j].x, vb3[j].y);
        }
    }
    __syncthreads();

    const int NIT = D_DIM / BK;   // 64
    for (int it = 0; it < NIT; it++) {
        bool pf = (it + 1 < NIT);
        int nk0 = (it + 1) * BK;
        if (pf) {
#pragma unroll
            for (int i = 0; i < 4; i++)
                va[i] = aptr[i] ? *(const float4*)(aptr[i] + nk0 + k4 * 4) : make_float4(0.f,0.f,0.f,0.f);
#pragma unroll
            for (int j = 0; j < 4; j++) {
                int kk = nk0 + (bg * 4 + j) * 2;
                vb1[j] = make_float2(W1[(size_t)kk * M_DIM + bn], W1[(size_t)(kk + 1) * M_DIM + bn]);
                vb3[j] = make_float2(W3[(size_t)kk * M_DIM + bn], W3[(size_t)(kk + 1) * M_DIM + bn]);
            }
        }
        // compute from buf[it&1]
        {
            const char* s = buf[it & 1];
#pragma unroll
            for (int ks = 0; ks < 2; ks++) {
                uint32_t aH[2][4], aL[2][4];
#pragma unroll
                for (int mi = 0; mi < 2; mi++) {
                    uint32_t o = (uint32_t)(m0 + mi * 16 + g) * PITCH + ks * 32 + q * 4;
                    aH[mi][0] = lds32(s + OFF_AH + o);
                    aH[mi][1] = lds32(s + OFF_AH + o + 8 * PITCH);
                    aH[mi][2] = lds32(s + OFF_AH + o + 16);
                    aH[mi][3] = lds32(s + OFF_AH + o + 8 * PITCH + 16);
                    aL[mi][0] = lds32(s + OFF_AL + o);
                    aL[mi][1] = lds32(s + OFF_AL + o + 8 * PITCH);
                    aL[mi][2] = lds32(s + OFF_AL + o + 16);
                    aL[mi][3] = lds32(s + OFF_AL + o + 8 * PITCH + 16);
                }
                uint32_t bh[4][2], bl[4][2];
                // ---- W1 ----
#pragma unroll
                for (int ni = 0; ni < 4; ni++) {
                    uint32_t o = (uint32_t)(n0w + ni * 8 + g) * PITCH + ks * 32 + q * 4;
                    bh[ni][0] = lds32(s + G1_B1H + o);
                    bh[ni][1] = lds32(s + G1_B1H + o + 16);
                    bl[ni][0] = lds32(s + G1_B1L + o);
                    bl[ni][1] = lds32(s + G1_B1L + o + 16);
                }
#pragma unroll
                for (int mi = 0; mi < 2; mi++)
#pragma unroll
                    for (int ni = 0; ni < 4; ni++) {
                        mma16816(c1[mi][ni], aH[mi], bh[ni]);
                        mma16816(c1[mi][ni], aL[mi], bh[ni]);
                        mma16816(c1[mi][ni], aH[mi], bl[ni]);
                    }
                // ---- W3 ----
#pragma unroll
                for (int ni = 0; ni < 4; ni++) {
                    uint32_t o = (uint32_t)(n0w + ni * 8 + g) * PITCH + ks * 32 + q * 4;
                    bh[ni][0] = lds32(s + G1_B3H + o);
                    bh[ni][1] = lds32(s + G1_B3H + o + 16);
                    bl[ni][0] = lds32(s + G1_B3L + o);
                    bl[ni][1] = lds32(s + G1_B3L + o + 16);
                }
#pragma unroll
                for (int mi = 0; mi < 2; mi++)
#pragma unroll
                    for (int ni = 0; ni < 4; ni++) {
                        mma16816(c3[mi][ni], aH[mi], bh[ni]);
                        mma16816(c3[mi][ni], aL[mi], bh[ni]);
                        mma16816(c3[mi][ni], aH[mi], bl[ni]);
                    }
            }
        }
        if (pf) {
            char* s = buf[(it + 1) & 1];
            uint32_t ab = (uint32_t)mrow * PITCH + k4 * 8;
#pragma unroll
            for (int i = 0; i < 4; i++) {
                uint32_t o = ab + i * 32 * PITCH;
                *(uint32_t*)(s + OFF_AH + o)     = phi(va[i].x, va[i].y);
                *(uint32_t*)(s + OFF_AH + o + 4) = phi(va[i].z, va[i].w);
                *(uint32_t*)(s + OFF_AL + o)     = plo(va[i].x, va[i].y);
                *(uint32_t*)(s + OFF_AL + o + 4) = plo(va[i].z, va[i].w);
            }
#pragma unroll
            for (int j = 0; j < 4; j++) {
                int kp = bg * 4 + j;
                uint32_t o = (uint32_t)bn * PITCH + kp * 4;
                *(uint32_t*)(s + G1_B1H + o) = phi(vb1[j].x, vb1[j].y);
                *(uint32_t*)(s + G1_B1L + o) = plo(vb1[j].x, vb1[j].y);
                *(uint32_t*)(s + G1_B3H + o) = phi(vb3[j].x, vb3[j].y);
                *(uint32_t*)(s + G1_B3L + o) = plo(vb3[j].x, vb3[j].y);
            }
        }
        __syncthreads();
    }

    // epilogue: silu(c1)*c3 -> g_hc (write all rows incl. padding zeros)
#pragma unroll
    for (int mi = 0; mi < 2; mi++)
#pragma unroll
        for (int ni = 0; ni < 4; ni++) {
            int rt = m0 + mi * 16 + g;
            int cb = nl + n0w + ni * 8 + q * 2;
            float* p0 = g_hc + (size_t)(r0 + rt) * CHUNK_M + cb;
            float2 o0;
            o0.x = silu(c1[mi][ni][0]) * c3[mi][ni][0];
            o0.y = silu(c1[mi][ni][1]) * c3[mi][ni][1];
            *(float2*)p0 = o0;
            float* p1 = g_hc + (size_t)(r0 + rt + 8) * CHUNK_M + cb;
            float2 o1;
            o1.x = silu(c1[mi][ni][2]) * c3[mi][ni][2];
            o1.y = silu(c1[mi][ni][3]) * c3[mi][ni][3];
            *(float2*)p1 = o1;
        }
}

// ============ GEMM2: out_rep (+)= h_chunk @ W2_chunk, scatter by replica ============
__global__ void __launch_bounds__(256)
k_gemm2(const float* __restrict__ w2, int c0, int first) {
    extern __shared__ char smem[];
    int bx = blockIdx.x;
    if (bx >= g_ntiles) return;
    int e  = g_tile_e[bx];
    int r0 = g_tile_row[bx];
    int n0 = blockIdx.y * 128;

    const float* W2 = w2 + (size_t)e * M_DIM * D_DIM + (size_t)c0 * D_DIM + n0;

    int tid = threadIdx.x;
    int w = tid >> 5, lane = tid & 31, g = lane >> 2, q = lane & 3;
    int m0 = (w & 3) * 32, n0w = (w >> 2) * 64;

    int k4 = tid & 7, mrow = tid >> 3;
    int bn = tid & 127, bh2 = tid >> 7;     // 2 halves of k-pairs

    const float* aptr[4];
#pragma unroll
    for (int i = 0; i < 4; i++)
        aptr[i] = g_hc + (size_t)(r0 + mrow + 32 * i) * CHUNK_M;

    char* buf[2] = { smem, smem + STG_BYTES };
    float c[2][8][4] = {{{0}}};

    float4 va[4]; float2 vb[8];
    // prologue stage 0
#pragma unroll
    for (int i = 0; i < 4; i++) va[i] = *(const float4*)(aptr[i] + k4 * 4);
#pragma unroll
    for (int j = 0; j < 8; j++) {
        int kk = (bh2 * 8 + j) * 2;
        vb[j] = make_float2(W2[(size_t)kk * D_DIM + bn], W2[(size_t)(kk + 1) * D_DIM + bn]);
    }
    {
        char* s = buf[0];
        uint32_t ab = (uint32_t)mrow * PITCH + k4 * 8;
#pragma unroll
        for (int i = 0; i < 4; i++) {
            uint32_t o = ab + i * 32 * PITCH;
            *(uint32_t*)(s + OFF_AH + o)     = phi(va[i].x, va[i].y);
            *(uint32_t*)(s + OFF_AH + o + 4) = phi(va[i].z, va[i].w);
            *(uint32_t*)(s + OFF_AL + o)     = plo(va[i].x, va[i].y);
            *(uint32_t*)(s + OFF_AL + o + 4) = plo(va[i].z, va[i].w);
        }
#pragma unroll
        for (int j = 0; j < 8; j++) {
            int kp = bh2 * 8 + j;
            uint32_t o = (uint32_t)bn * PITCH + kp * 4;
            *(uint32_t*)(s + G2_BH + o) = phi(vb[j].x, vb[j].y);
            *(uint32_t*)(s + G2_BL + o) = plo(vb[j].x, vb[j].y);
        }
    }
    __syncthreads();

    const int NIT = CHUNK_M / BK;  // 56
    for (int it = 0; it < NIT; it++) {
        bool pf = (it + 1 < NIT);
        int nk0 = (it + 1) * BK;
        if (pf) {
#pragma unroll
            for (int i = 0; i < 4; i++) va[i] = *(const float4*)(aptr[i] + nk0 + k4 * 4);
#pragma unroll
            for (int j = 0; j < 8; j++) {
                int kk = nk0 + (bh2 * 8 + j) * 2;
                vb[j] = make_float2(W2[(size_t)kk * D_DIM + bn], W2[(size_t)(kk + 1) * D_DIM + bn]);
            }
        }
        {
            const char* s = buf[it & 1];
#pragma unroll
            for (int ks = 0; ks < 2; ks++) {
                uint32_t aH[2][4], aL[2][4];
#pragma unroll
                for (int mi = 0; mi < 2; mi++) {
                    uint32_t o = (uint32_t)(m0 + mi * 16 + g) * PITCH + ks * 32 + q * 4;
                    aH[mi][0] = lds32(s + OFF_AH + o);
                    aH[mi][1] = lds32(s + OFF_AH + o + 8 * PITCH);
                    aH[mi][2] = lds32(s + OFF_AH + o + 16);
                    aH[mi][3] = lds32(s + OFF_AH + o + 8 * PITCH + 16);
                    aL[mi][0] = lds32(s + OFF_AL + o);
                    aL[mi][1] = lds32(s + OFF_AL + o + 8 * PITCH);
                    aL[mi][2] = lds32(s + OFF_AL + o + 16);
                    aL[mi][3] = lds32(s + OFF_AL + o + 8 * PITCH + 16);
                }
#pragma unroll
                for (int ni = 0; ni < 8; ni++) {
                    uint32_t o = (uint32_t)(n0w + ni * 8 + g) * PITCH + ks * 32 + q * 4;
                    uint32_t bHf[2], bLf[2];
                    bHf[0] = lds32(s + G2_BH + o);
                    bHf[1] = lds32(s + G2_BH + o + 16);
                    bLf[0] = lds32(s + G2_BL + o);
                    bLf[1] = lds32(s + G2_BL + o + 16);
#pragma unroll
                    for (int mi = 0; mi < 2; mi++) {
                        mma16816(c[mi][ni], aH[mi], bHf);
                        mma16816(c[mi][ni], aL[mi], bHf);
                        mma16816(c[mi][ni], aH[mi], bLf);
                    }
                }
            }
        }
        if (pf) {
            char* s = buf[(it + 1) & 1];
            uint32_t ab = (uint32_t)mrow * PITCH + k4 * 8;
#pragma unroll
            for (int i = 0; i < 4; i++) {
                uint32_t o = ab + i * 32 * PITCH;
                *(uint32_t*)(s + OFF_AH + o)     = phi(va[i].x, va[i].y);
                *(uint32_t*)(s + OFF_AH + o + 4) = phi(va[i].z, va[i].w);
                *(uint32_t*)(s + OFF_AL + o)     = plo(va[i].x, va[i].y);
                *(uint32_t*)(s + OFF_AL + o + 4) = plo(va[i].z, va[i].w);
            }
#pragma unroll
            for (int j = 0; j < 8; j++) {
                int kp = bh2 * 8 + j;
                uint32_t o = (uint32_t)bn * PITCH + kp * 4;
                *(uint32_t*)(s + G2_BH + o) = phi(vb[j].x, vb[j].y);
                *(uint32_t*)(s + G2_BL + o) = plo(vb[j].x, vb[j].y);
            }
        }
        __syncthreads();
    }

    // epilogue: accumulate into g_outrep, scatter by replica
#pragma unroll
    for (int mi = 0; mi < 2; mi++) {
        int rt = m0 + mi * 16 + g;
#pragma unroll
        for (int half = 0; half < 2; half++) {
            int row = rt + half * 8;
            int repl = g_repl_map[r0 + row];
            if (repl < 0) continue;
#pragma unroll
            for (int ni = 0; ni < 8; ni++) {
                int cb = n0 + n0w + ni * 8 + q * 2;
                float* p = g_outrep + (size_t)repl * D_DIM + cb;
                float2 v;
                v.x = c[mi][ni][half * 2 + 0];
                v.y = c[mi][ni][half * 2 + 1];
                if (!first) {
                    float2 old = *(const float2*)p;
                    v.x += old.x; v.y += old.y;
                }
                *(float2*)p = v;
            }
        }
    }
}

// ---------------- combine ----------------
__global__ void k_combine(float* __restrict__ out) {
    int i = blockIdx.x * blockDim.x + threadIdx.x;
    int t = i >> 9;
    int c = (i & 511) * 4;
    if (t >= T_TOK) return;
    float w0 = g_tw[2 * t], w1 = g_tw[2 * t + 1];
    float4 a = *(const float4*)&g_outrep[(size_t)(2 * t) * D_DIM + c];
    float4 b = *(const float4*)&g_outrep[(size_t)(2 * t + 1) * D_DIM + c];
    float4 o;
    o.x = w0 * a.x + w1 * b.x;
    o.y = w0 * a.y + w1 * b.y;
    o.z = w0 * a.z + w1 * b.z;
    o.w = w0 * a.w + w1 * b.w;
    *(float4*)&out[(size_t)t * D_DIM + c] = o;
}

// ---------------- launch ----------------
extern "C" void kernel_launch(void* const* d_in, const int* in_sizes, int n_in,
                              void* d_out, int out_size) {
    const float* x  = (const float*)d_in[0];
    const float* gw = (const float*)d_in[1];
    const float* w1 = (const float*)d_in[2];
    const float* w2 = (const float*)d_in[3];
    const float* w3 = (const float*)d_in[4];
    float* out = (float*)d_out;

    static int configured = 0;
    if (!configured) {
        cudaFuncSetAttribute(k_gemm1, cudaFuncAttributeMaxDynamicSharedMemorySize, SMEM_TOTAL);
        cudaFuncSetAttribute(k_gemm2, cudaFuncAttributeMaxDynamicSharedMemorySize, SMEM_TOTAL);
        configured = 1;
    }

    k_init<<<1, 256>>>();
    k_router<<<T_TOK / 8, 256>>>(x, gw);
    k_perm<<<1, 256>>>();
    for (int c = 0; c < N_CHUNKS; c++) {
        int c0 = c * CHUNK_M;
        k_gemm1<<<dim3(MAX_RT, CHUNK_M / 64), 256, SMEM_TOTAL>>>(x, w1, w3, c0);
        k_gemm2<<<dim3(MAX_RT, D_DIM / 128), 256, SMEM_TOTAL>>>(w2, c0, c == 0);
    }
    k_combine<<<(T_TOK * D_DIM / 4) / 256, 256>>>(out);
}

// round 10
// speedup vs baseline: 1.5657x; 1.0868x over previous
#include <cuda_runtime.h>
#include <cuda_bf16.h>
#include <stdint.h>
#include <math.h>

// ---------------- problem constants ----------------
#define D_DIM 2048
#define M_DIM 7168
#define E_NUM 8
#define T_TOK 4096
#define TR    (T_TOK * 2)

#define TILE_M 128
#define CHUNK_M 1792
#define N_CHUNKS (M_DIM / CHUNK_M)          // 4
#define PADROWS  (TR + E_NUM * TILE_M)      // 9216
#define MAX_RT   80

#define BK 32
#define PITCH 72                            // smem row pitch bytes

// per-stage smem layout (bytes) — both gemms use 27648-byte stages
#define OFF_AH 0
#define OFF_AL 9216
#define G1_B1H 18432
#define G1_B1L 20736
#define G1_B3H 23040
#define G1_B3L 25344
#define G2_BH  18432
#define G2_BL  23040
#define STG_BYTES 27648
#define SMEM_TOTAL (2 * STG_BYTES)          // 55296

// ---------------- static device scratch ----------------
__device__ float g_hc[(size_t)PADROWS * CHUNK_M];   // hidden chunk, row-major, 66 MB
__device__ float g_outrep[(size_t)TR * D_DIM];      // per-replica output, 67 MB
__device__ int   g_row_map[PADROWS];
__device__ int   g_repl_map[PADROWS];
__device__ int   g_eidx[TR];
__device__ float g_tw[TR];
__device__ int   g_tile_e[MAX_RT];
__device__ int   g_tile_row[MAX_RT];
__device__ int   g_ntiles;

// ---------------- helpers ----------------
__device__ __forceinline__ uint32_t phi(float a, float b) {
    __nv_bfloat162 t = __floats2bfloat162_rn(a, b);
    return *reinterpret_cast<uint32_t*>(&t);
}
__device__ __forceinline__ uint32_t plo(float a, float b) {
    float ah = __bfloat162float(__float2bfloat16_rn(a));
    float bh = __bfloat162float(__float2bfloat16_rn(b));
    return phi(a - ah, b - bh);
}
__device__ __forceinline__ void mma16816(float* c, const uint32_t* a, const uint32_t* b) {
    asm volatile(
        "mma.sync.aligned.m16n8k16.row.col.f32.bf16.bf16.f32 "
        "{%0,%1,%2,%3}, {%4,%5,%6,%7}, {%8,%9}, {%0,%1,%2,%3};"
        : "+f"(c[0]), "+f"(c[1]), "+f"(c[2]), "+f"(c[3])
        : "r"(a[0]), "r"(a[1]), "r"(a[2]), "r"(a[3]), "r"(b[0]), "r"(b[1]));
}
__device__ __forceinline__ uint32_t lds32(const char* p) {
    return *reinterpret_cast<const uint32_t*>(p);
}
__device__ __forceinline__ float silu(float v) {
    return v / (1.f + __expf(-v));
}

// ---------------- init ----------------
__global__ void k_init() {
    for (int i = threadIdx.x; i < PADROWS; i += blockDim.x) {
        g_row_map[i]  = -1;
        g_repl_map[i] = -1;
    }
}

// ---------------- router ----------------
__global__ void k_router(const float* __restrict__ x, const float* __restrict__ gw) {
    int warp = (blockIdx.x * blockDim.x + threadIdx.x) >> 5;
    int lane = threadIdx.x & 31;
    if (warp >= T_TOK) return;
    const float* xr = x + (size_t)warp * D_DIM;
    float acc[8] = {0.f,0.f,0.f,0.f,0.f,0.f,0.f,0.f};
    for (int k = lane; k < D_DIM; k += 32) {
        float xv = xr[k];
        const float4* g4 = (const float4*)(gw + (size_t)k * E_NUM);
        float4 g0 = g4[0], g1 = g4[1];
        acc[0] += xv * g0.x; acc[1] += xv * g0.y; acc[2] += xv * g0.z; acc[3] += xv * g0.w;
        acc[4] += xv * g1.x; acc[5] += xv * g1.y; acc[6] += xv * g1.z; acc[7] += xv * g1.w;
    }
#pragma unroll
    for (int e = 0; e < 8; e++)
#pragma unroll
        for (int o = 16; o > 0; o >>= 1)
            acc[e] += __shfl_xor_sync(0xFFFFFFFFu, acc[e], o);
    if (lane == 0) {
        int e0 = 0; float l0 = acc[0];
#pragma unroll
        for (int e = 1; e < 8; e++) if (acc[e] > l0) { l0 = acc[e]; e0 = e; }
        int e1 = -1; float l1 = -3.4e38f;
#pragma unroll
        for (int e = 0; e < 8; e++) if (e != e0 && acc[e] > l1) { l1 = acc[e]; e1 = e; }
        float w0 = 1.f / (1.f + __expf(l1 - l0));
        g_eidx[2 * warp] = e0; g_eidx[2 * warp + 1] = e1;
        g_tw[2 * warp] = w0;   g_tw[2 * warp + 1] = 1.f - w0;
    }
}

// ---------------- permutation + tile list ----------------
__global__ void k_perm() {
    __shared__ int sc[E_NUM], soff[E_NUM], scur[E_NUM];
    int t = threadIdx.x;
    if (t < E_NUM) { sc[t] = 0; scur[t] = 0; }
    __syncthreads();
    for (int r = t; r < TR; r += blockDim.x) atomicAdd(&sc[g_eidx[r]], 1);
    __syncthreads();
    if (t == 0) {
        int off = 0, nt = 0;
        for (int e = 0; e < E_NUM; e++) {
            soff[e] = off;
            int cnt = sc[e];
            for (int t0 = 0; t0 < cnt; t0 += TILE_M) {
                g_tile_e[nt] = e; g_tile_row[nt] = off + t0; nt++;
            }
            off += ((cnt + TILE_M - 1) / TILE_M) * TILE_M;
        }
        g_ntiles = nt;
    }
    __syncthreads();
    for (int r = t; r < TR; r += blockDim.x) {
        int e = g_eidx[r];
        int pos = soff[e] + atomicAdd(&scur[e], 1);
        g_row_map[pos]  = r >> 1;
        g_repl_map[pos] = r;
    }
}

// ============ GEMM1: CTA 128m x 32n, warp 32m x 16n over W1 & W3 ============
__global__ void __launch_bounds__(256, 2)
k_gemm1(const float* __restrict__ x,
        const float* __restrict__ w1,
        const float* __restrict__ w3, int c0) {
    extern __shared__ char smem[];
    int bx = blockIdx.x;
    if (bx >= g_ntiles) return;
    int e  = g_tile_e[bx];
    int r0 = g_tile_row[bx];
    int nl = blockIdx.y * 32;               // chunk-local col base

    const float* W1 = w1 + (size_t)e * D_DIM * M_DIM + c0 + nl;
    const float* W3 = w3 + (size_t)e * D_DIM * M_DIM + c0 + nl;

    int tid = threadIdx.x;
    int w = tid >> 5, lane = tid & 31, g = lane >> 2, q = lane & 3;
    int m0 = (w & 3) * 32, n0w = (w >> 2) * 16;

    // staging indices
    int k4 = tid & 7, mrow = tid >> 3;      // A loader
    int bn = tid & 31, kg = tid >> 5;       // B loader: col bn, k-pair base kg*2

    const float* aptr[4];
#pragma unroll
    for (int i = 0; i < 4; i++) {
        int gr = g_row_map[r0 + mrow + 32 * i];
        aptr[i] = (gr >= 0) ? x + (size_t)gr * D_DIM : (const float*)0;
    }

    char* buf[2] = { smem, smem + STG_BYTES };
    float c1[2][2][4] = {{{0}}}, c3[2][2][4] = {{{0}}};

    float4 va[4]; float2 vb1[2], vb3[2];
#pragma unroll
    for (int i = 0; i < 4; i++)
        va[i] = aptr[i] ? *(const float4*)(aptr[i] + k4 * 4) : make_float4(0.f,0.f,0.f,0.f);
#pragma unroll
    for (int j = 0; j < 2; j++) {
        int kk = (kg * 2 + j) * 2;
        vb1[j] = make_float2(W1[(size_t)kk * M_DIM + bn], W1[(size_t)(kk + 1) * M_DIM + bn]);
        vb3[j] = make_float2(W3[(size_t)kk * M_DIM + bn], W3[(size_t)(kk + 1) * M_DIM + bn]);
    }
    {
        char* s = buf[0];
        uint32_t ab = (uint32_t)mrow * PITCH + k4 * 8;
#pragma unroll
        for (int i = 0; i < 4; i++) {
            uint32_t o = ab + i * 32 * PITCH;
            *(uint32_t*)(s + OFF_AH + o)     = phi(va[i].x, va[i].y);
            *(uint32_t*)(s + OFF_AH + o + 4) = phi(va[i].z, va[i].w);
            *(uint32_t*)(s + OFF_AL + o)     = plo(va[i].x, va[i].y);
            *(uint32_t*)(s + OFF_AL + o + 4) = plo(va[i].z, va[i].w);
        }
#pragma unroll
        for (int j = 0; j < 2; j++) {
            int kp = kg * 2 + j;
            uint32_t o = (uint32_t)bn * PITCH + kp * 4;
            *(uint32_t*)(s + G1_B1H + o) = phi(vb1[j].x, vb1[j].y);
            *(uint32_t*)(s + G1_B1L + o) = plo(vb1[j].x, vb1[j].y);
            *(uint32_t*)(s + G1_B3H + o) = phi(vb3[j].x, vb3[j].y);
            *(uint32_t*)(s + G1_B3L + o) = plo(vb3[j].x, vb3[j].y);
        }
    }
    __syncthreads();

    const int NIT = D_DIM / BK;   // 64
    for (int it = 0; it < NIT; it++) {
        bool pf = (it + 1 < NIT);
        int nk0 = (it + 1) * BK;
        if (pf) {
#pragma unroll
            for (int i = 0; i < 4; i++)
                va[i] = aptr[i] ? *(const float4*)(aptr[i] + nk0 + k4 * 4) : make_float4(0.f,0.f,0.f,0.f);
#pragma unroll
            for (int j = 0; j < 2; j++) {
                int kk = nk0 + (kg * 2 + j) * 2;
                vb1[j] = make_float2(W1[(size_t)kk * M_DIM + bn], W1[(size_t)(kk + 1) * M_DIM + bn]);
                vb3[j] = make_float2(W3[(size_t)kk * M_DIM + bn], W3[(size_t)(kk + 1) * M_DIM + bn]);
            }
        }
        {
            const char* s = buf[it & 1];
#pragma unroll
            for (int ks = 0; ks < 2; ks++) {
                uint32_t aH[2][4], aL[2][4];
#pragma unroll
                for (int mi = 0; mi < 2; mi++) {
                    uint32_t o = (uint32_t)(m0 + mi * 16 + g) * PITCH + ks * 32 + q * 4;
                    aH[mi][0] = lds32(s + OFF_AH + o);
                    aH[mi][1] = lds32(s + OFF_AH + o + 8 * PITCH);
                    aH[mi][2] = lds32(s + OFF_AH + o + 16);
                    aH[mi][3] = lds32(s + OFF_AH + o + 8 * PITCH + 16);
                    aL[mi][0] = lds32(s + OFF_AL + o);
                    aL[mi][1] = lds32(s + OFF_AL + o + 8 * PITCH);
                    aL[mi][2] = lds32(s + OFF_AL + o + 16);
                    aL[mi][3] = lds32(s + OFF_AL + o + 8 * PITCH + 16);
                }
                uint32_t bh[2][2], bl[2][2];
#pragma unroll
                for (int ni = 0; ni < 2; ni++) {
                    uint32_t o = (uint32_t)(n0w + ni * 8 + g) * PITCH + ks * 32 + q * 4;
                    bh[ni][0] = lds32(s + G1_B1H + o);
                    bh[ni][1] = lds32(s + G1_B1H + o + 16);
                    bl[ni][0] = lds32(s + G1_B1L + o);
                    bl[ni][1] = lds32(s + G1_B1L + o + 16);
                }
#pragma unroll
                for (int mi = 0; mi < 2; mi++)
#pragma unroll
                    for (int ni = 0; ni < 2; ni++) {
                        mma16816(c1[mi][ni], aH[mi], bh[ni]);
                        mma16816(c1[mi][ni], aL[mi], bh[ni]);
                        mma16816(c1[mi][ni], aH[mi], bl[ni]);
                    }
#pragma unroll
                for (int ni = 0; ni < 2; ni++) {
                    uint32_t o = (uint32_t)(n0w + ni * 8 + g) * PITCH + ks * 32 + q * 4;
                    bh[ni][0] = lds32(s + G1_B3H + o);
                    bh[ni][1] = lds32(s + G1_B3H + o + 16);
                    bl[ni][0] = lds32(s + G1_B3L + o);
                    bl[ni][1] = lds32(s + G1_B3L + o + 16);
                }
#pragma unroll
                for (int mi = 0; mi < 2; mi++)
#pragma unroll
                    for (int ni = 0; ni < 2; ni++) {
                        mma16816(c3[mi][ni], aH[mi], bh[ni]);
                        mma16816(c3[mi][ni], aL[mi], bh[ni]);
                        mma16816(c3[mi][ni], aH[mi], bl[ni]);
                    }
            }
        }
        if (pf) {
            char* s = buf[(it + 1) & 1];
            uint32_t ab = (uint32_t)mrow * PITCH + k4 * 8;
#pragma unroll
            for (int i = 0; i < 4; i++) {
                uint32_t o = ab + i * 32 * PITCH;
                *(uint32_t*)(s + OFF_AH + o)     = phi(va[i].x, va[i].y);
                *(uint32_t*)(s + OFF_AH + o + 4) = phi(va[i].z, va[i].w);
                *(uint32_t*)(s + OFF_AL + o)     = plo(va[i].x, va[i].y);
                *(uint32_t*)(s + OFF_AL + o + 4) = plo(va[i].z, va[i].w);
            }
#pragma unroll
            for (int j = 0; j < 2; j++) {
                int kp = kg * 2 + j;
                uint32_t o = (uint32_t)bn * PITCH + kp * 4;
                *(uint32_t*)(s + G1_B1H + o) = phi(vb1[j].x, vb1[j].y);
                *(uint32_t*)(s + G1_B1L + o) = plo(vb1[j].x, vb1[j].y);
                *(uint32_t*)(s + G1_B3H + o) = phi(vb3[j].x, vb3[j].y);
                *(uint32_t*)(s + G1_B3L + o) = plo(vb3[j].x, vb3[j].y);
            }
        }
        __syncthreads();
    }

    // epilogue
#pragma unroll
    for (int mi = 0; mi < 2; mi++)
#pragma unroll
        for (int ni = 0; ni < 2; ni++) {
            int rt = m0 + mi * 16 + g;
            int cb = nl + n0w + ni * 8 + q * 2;
            float* p0 = g_hc + (size_t)(r0 + rt) * CHUNK_M + cb;
            float2 o0;
            o0.x = silu(c1[mi][ni][0]) * c3[mi][ni][0];
            o0.y = silu(c1[mi][ni][1]) * c3[mi][ni][1];
            *(float2*)p0 = o0;
            float* p1 = g_hc + (size_t)(r0 + rt + 8) * CHUNK_M + cb;
            float2 o1;
            o1.x = silu(c1[mi][ni][2]) * c3[mi][ni][2];
            o1.y = silu(c1[mi][ni][3]) * c3[mi][ni][3];
            *(float2*)p1 = o1;
        }
}

// ============ GEMM2: CTA 128m x 64n, warp 32m x 32n ============
__global__ void __launch_bounds__(256, 2)
k_gemm2(const float* __restrict__ w2, int c0, int first) {
    extern __shared__ char smem[];
    int bx = blockIdx.x;
    if (bx >= g_ntiles) return;
    int e  = g_tile_e[bx];
    int r0 = g_tile_row[bx];
    int n0 = blockIdx.y * 64;

    const float* W2 = w2 + (size_t)e * M_DIM * D_DIM + (size_t)c0 * D_DIM + n0;

    int tid = threadIdx.x;
    int w = tid >> 5, lane = tid & 31, g = lane >> 2, q = lane & 3;
    int m0 = (w & 3) * 32, n0w = (w >> 2) * 32;

    int k4 = tid & 7, mrow = tid >> 3;
    int bn = tid & 63, kg = tid >> 6;       // B: col bn, k-pair base kg*4

    const float* aptr[4];
#pragma unroll
    for (int i = 0; i < 4; i++)
        aptr[i] = g_hc + (size_t)(r0 + mrow + 32 * i) * CHUNK_M;

    char* buf[2] = { smem, smem + STG_BYTES };
    float c[2][4][4] = {{{0}}};

    float4 va[4]; float2 vb[4];
#pragma unroll
    for (int i = 0; i < 4; i++) va[i] = *(const float4*)(aptr[i] + k4 * 4);
#pragma unroll
    for (int j = 0; j < 4; j++) {
        int kk = (kg * 4 + j) * 2;
        vb[j] = make_float2(W2[(size_t)kk * D_DIM + bn], W2[(size_t)(kk + 1) * D_DIM + bn]);
    }
    {
        char* s = buf[0];
        uint32_t ab = (uint32_t)mrow * PITCH + k4 * 8;
#pragma unroll
        for (int i = 0; i < 4; i++) {
            uint32_t o = ab + i * 32 * PITCH;
            *(uint32_t*)(s + OFF_AH + o)     = phi(va[i].x, va[i].y);
            *(uint32_t*)(s + OFF_AH + o + 4) = phi(va[i].z, va[i].w);
            *(uint32_t*)(s + OFF_AL + o)     = plo(va[i].x, va[i].y);
            *(uint32_t*)(s + OFF_AL + o + 4) = plo(va[i].z, va[i].w);
        }
#pragma unroll
        for (int j = 0; j < 4; j++) {
            int kp = kg * 4 + j;
            uint32_t o = (uint32_t)bn * PITCH + kp * 4;
            *(uint32_t*)(s + G2_BH + o) = phi(vb[j].x, vb[j].y);
            *(uint32_t*)(s + G2_BL + o) = plo(vb[j].x, vb[j].y);
        }
    }
    __syncthreads();

    const int NIT = CHUNK_M / BK;  // 56
    for (int it = 0; it < NIT; it++) {
        bool pf = (it + 1 < NIT);
        int nk0 = (it + 1) * BK;
        if (pf) {
#pragma unroll
            for (int i = 0; i < 4; i++) va[i] = *(const float4*)(aptr[i] + nk0 + k4 * 4);
#pragma unroll
            for (int j = 0; j < 4; j++) {
                int kk = nk0 + (kg * 4 + j) * 2;
                vb[j] = make_float2(W2[(size_t)kk * D_DIM + bn], W2[(size_t)(kk + 1) * D_DIM + bn]);
            }
        }
        {
            const char* s = buf[it & 1];
#pragma unroll
            for (int ks = 0; ks < 2; ks++) {
                uint32_t aH[2][4], aL[2][4];
#pragma unroll
                for (int mi = 0; mi < 2; mi++) {
                    uint32_t o = (uint32_t)(m0 + mi * 16 + g) * PITCH + ks * 32 + q * 4;
                    aH[mi][0] = lds32(s + OFF_AH + o);
                    aH[mi][1] = lds32(s + OFF_AH + o + 8 * PITCH);
                    aH[mi][2] = lds32(s + OFF_AH + o + 16);
                    aH[mi][3] = lds32(s + OFF_AH + o + 8 * PITCH + 16);
                    aL[mi][0] = lds32(s + OFF_AL + o);
                    aL[mi][1] = lds32(s + OFF_AL + o + 8 * PITCH);
                    aL[mi][2] = lds32(s + OFF_AL + o + 16);
                    aL[mi][3] = lds32(s + OFF_AL + o + 8 * PITCH + 16);
                }
#pragma unroll
                for (int ni = 0; ni < 4; ni++) {
                    uint32_t o = (uint32_t)(n0w + ni * 8 + g) * PITCH + ks * 32 + q * 4;
                    uint32_t bHf[2], bLf[2];
                    bHf[0] = lds32(s + G2_BH + o);
                    bHf[1] = lds32(s + G2_BH + o + 16);
                    bLf[0] = lds32(s + G2_BL + o);
                    bLf[1] = lds32(s + G2_BL + o + 16);
#pragma unroll
                    for (int mi = 0; mi < 2; mi++) {
                        mma16816(c[mi][ni], aH[mi], bHf);
                        mma16816(c[mi][ni], aL[mi], bHf);
                        mma16816(c[mi][ni], aH[mi], bLf);
                    }
                }
            }
        }
        if (pf) {
            char* s = buf[(it + 1) & 1];
            uint32_t ab = (uint32_t)mrow * PITCH + k4 * 8;
#pragma unroll
            for (int i = 0; i < 4; i++) {
                uint32_t o = ab + i * 32 * PITCH;
                *(uint32_t*)(s + OFF_AH + o)     = phi(va[i].x, va[i].y);
                *(uint32_t*)(s + OFF_AH + o + 4) = phi(va[i].z, va[i].w);
                *(uint32_t*)(s + OFF_AL + o)     = plo(va[i].x, va[i].y);
                *(uint32_t*)(s + OFF_AL + o + 4) = plo(va[i].z, va[i].w);
            }
#pragma unroll
            for (int j = 0; j < 4; j++) {
                int kp = kg * 4 + j;
                uint32_t o = (uint32_t)bn * PITCH + kp * 4;
                *(uint32_t*)(s + G2_BH + o) = phi(vb[j].x, vb[j].y);
                *(uint32_t*)(s + G2_BL + o) = plo(vb[j].x, vb[j].y);
            }
        }
        __syncthreads();
    }

    // epilogue: accumulate into g_outrep, scatter by replica
#pragma unroll
    for (int mi = 0; mi < 2; mi++) {
        int rt = m0 + mi * 16 + g;
#pragma unroll
        for (int half = 0; half < 2; half++) {
            int row = rt + half * 8;
            int repl = g_repl_map[r0 + row];
            if (repl < 0) continue;
#pragma unroll
            for (int ni = 0; ni < 4; ni++) {
                int cb = n0 + n0w + ni * 8 + q * 2;
                float* p = g_outrep + (size_t)repl * D_DIM + cb;
                float2 v;
                v.x = c[mi][ni][half * 2 + 0];
                v.y = c[mi][ni][half * 2 + 1];
                if (!first) {
                    float2 old = *(const float2*)p;
                    v.x += old.x; v.y += old.y;
                }
                *(float2*)p = v;
            }
        }
    }
}

// ---------------- combine ----------------
__global__ void k_combine(float* __restrict__ out) {
    int i = blockIdx.x * blockDim.x + threadIdx.x;
    int t = i >> 9;
    int c = (i & 511) * 4;
    if (t >= T_TOK) return;
    float w0 = g_tw[2 * t], w1 = g_tw[2 * t + 1];
    float4 a = *(const float4*)&g_outrep[(size_t)(2 * t) * D_DIM + c];
    float4 b = *(const float4*)&g_outrep[(size_t)(2 * t + 1) * D_DIM + c];
    float4 o;
    o.x = w0 * a.x + w1 * b.x;
    o.y = w0 * a.y + w1 * b.y;
    o.z = w0 * a.z + w1 * b.z;
    o.w = w0 * a.w + w1 * b.w;
    *(float4*)&out[(size_t)t * D_DIM + c] = o;
}

// ---------------- launch ----------------
extern "C" void kernel_launch(void* const* d_in, const int* in_sizes, int n_in,
                              void* d_out, int out_size) {
    const float* x  = (const float*)d_in[0];
    const float* gw = (const float*)d_in[1];
    const float* w1 = (const float*)d_in[2];
    const float* w2 = (const float*)d_in[3];
    const float* w3 = (const float*)d_in[4];
    float* out = (float*)d_out;

    static int configured = 0;
    if (!configured) {
        cudaFuncSetAttribute(k_gemm1, cudaFuncAttributeMaxDynamicSharedMemorySize, SMEM_TOTAL);
        cudaFuncSetAttribute(k_gemm2, cudaFuncAttributeMaxDynamicSharedMemorySize, SMEM_TOTAL);
        configured = 1;
    }

    k_init<<<1, 256>>>();
    k_router<<<T_TOK / 8, 256>>>(x, gw);
    k_perm<<<1, 256>>>();
    for (int c = 0; c < N_CHUNKS; c++) {
        int c0 = c * CHUNK_M;
        k_gemm1<<<dim3(MAX_RT, CHUNK_M / 32), 256, SMEM_TOTAL>>>(x, w1, w3, c0);
        k_gemm2<<<dim3(MAX_RT, D_DIM / 64), 256, SMEM_TOTAL>>>(w2, c0, c == 0);
    }
    k_combine<<<(T_TOK * D_DIM / 4) / 256, 256>>>(out);
}

// round 11
// speedup vs baseline: 1.9007x; 1.2140x over previous
#include <cuda_runtime.h>
#include <cuda_bf16.h>
#include <stdint.h>
#include <math.h>

// ---------------- problem constants ----------------
#define D_DIM 2048
#define M_DIM 7168
#define E_NUM 8
#define T_TOK 4096
#define TR    (T_TOK * 2)

#define TILE_M 128
#define CHUNK_M 1792
#define N_CHUNKS (M_DIM / CHUNK_M)          // 4
#define PADROWS  (TR + E_NUM * TILE_M)      // 9216
#define MAX_RT   80

#define BK 32
#define PITCH 80                            // smem row pitch bytes = 20 banks (conflict-free)

// per-stage smem layout (bytes)
#define OFF_AH 0
#define OFF_AL 10240
#define G1_B1H 20480
#define G1_B1L 23040
#define G1_B3H 25600
#define G1_B3L 28160
#define G2_BH  20480
#define G2_BL  25600
#define STG_BYTES 30720
#define SMEM_TOTAL (2 * STG_BYTES)          // 61440

// ---------------- static device scratch ----------------
__device__ float g_hc[(size_t)PADROWS * CHUNK_M];   // hidden chunk, row-major, 66 MB
__device__ float g_outrep[(size_t)TR * D_DIM];      // per-replica output, 67 MB
__device__ int   g_row_map[PADROWS];
__device__ int   g_repl_map[PADROWS];
__device__ int   g_eidx[TR];
__device__ float g_tw[TR];
__device__ int   g_tile_e[MAX_RT];
__device__ int   g_tile_row[MAX_RT];
__device__ int   g_ntiles;

// ---------------- helpers ----------------
__device__ __forceinline__ uint32_t phi(float a, float b) {
    __nv_bfloat162 t = __floats2bfloat162_rn(a, b);
    return *reinterpret_cast<uint32_t*>(&t);
}
__device__ __forceinline__ uint32_t plo(float a, float b) {
    float ah = __bfloat162float(__float2bfloat16_rn(a));
    float bh = __bfloat162float(__float2bfloat16_rn(b));
    return phi(a - ah, b - bh);
}
__device__ __forceinline__ void mma16816(float* c, const uint32_t* a, const uint32_t* b) {
    asm volatile(
        "mma.sync.aligned.m16n8k16.row.col.f32.bf16.bf16.f32 "
        "{%0,%1,%2,%3}, {%4,%5,%6,%7}, {%8,%9}, {%0,%1,%2,%3};"
        : "+f"(c[0]), "+f"(c[1]), "+f"(c[2]), "+f"(c[3])
        : "r"(a[0]), "r"(a[1]), "r"(a[2]), "r"(a[3]), "r"(b[0]), "r"(b[1]));
}
__device__ __forceinline__ uint32_t lds32(const char* p) {
    return *reinterpret_cast<const uint32_t*>(p);
}
__device__ __forceinline__ float silu(float v) {
    return v / (1.f + __expf(-v));
}

// ---------------- init ----------------
__global__ void k_init() {
    for (int i = threadIdx.x; i < PADROWS; i += blockDim.x) {
        g_row_map[i]  = -1;
        g_repl_map[i] = -1;
    }
}

// ---------------- router ----------------
__global__ void k_router(const float* __restrict__ x, const float* __restrict__ gw) {
    int warp = (blockIdx.x * blockDim.x + threadIdx.x) >> 5;
    int lane = threadIdx.x & 31;
    if (warp >= T_TOK) return;
    const float* xr = x + (size_t)warp * D_DIM;
    float acc[8] = {0.f,0.f,0.f,0.f,0.f,0.f,0.f,0.f};
    for (int k = lane; k < D_DIM; k += 32) {
        float xv = xr[k];
        const float4* g4 = (const float4*)(gw + (size_t)k * E_NUM);
        float4 g0 = g4[0], g1 = g4[1];
        acc[0] += xv * g0.x; acc[1] += xv * g0.y; acc[2] += xv * g0.z; acc[3] += xv * g0.w;
        acc[4] += xv * g1.x; acc[5] += xv * g1.y; acc[6] += xv * g1.z; acc[7] += xv * g1.w;
    }
#pragma unroll
    for (int e = 0; e < 8; e++)
#pragma unroll
        for (int o = 16; o > 0; o >>= 1)
            acc[e] += __shfl_xor_sync(0xFFFFFFFFu, acc[e], o);
    if (lane == 0) {
        int e0 = 0; float l0 = acc[0];
#pragma unroll
        for (int e = 1; e < 8; e++) if (acc[e] > l0) { l0 = acc[e]; e0 = e; }
        int e1 = -1; float l1 = -3.4e38f;
#pragma unroll
        for (int e = 0; e < 8; e++) if (e != e0 && acc[e] > l1) { l1 = acc[e]; e1 = e; }
        float w0 = 1.f / (1.f + __expf(l1 - l0));
        g_eidx[2 * warp] = e0; g_eidx[2 * warp + 1] = e1;
        g_tw[2 * warp] = w0;   g_tw[2 * warp + 1] = 1.f - w0;
    }
}

// ---------------- permutation + tile list ----------------
__global__ void k_perm() {
    __shared__ int sc[E_NUM], soff[E_NUM], scur[E_NUM];
    int t = threadIdx.x;
    if (t < E_NUM) { sc[t] = 0; scur[t] = 0; }
    __syncthreads();
    for (int r = t; r < TR; r += blockDim.x) atomicAdd(&sc[g_eidx[r]], 1);
    __syncthreads();
    if (t == 0) {
        int off = 0, nt = 0;
        for (int e = 0; e < E_NUM; e++) {
            soff[e] = off;
            int cnt = sc[e];
            for (int t0 = 0; t0 < cnt; t0 += TILE_M) {
                g_tile_e[nt] = e; g_tile_row[nt] = off + t0; nt++;
            }
            off += ((cnt + TILE_M - 1) / TILE_M) * TILE_M;
        }
        g_ntiles = nt;
    }
    __syncthreads();
    for (int r = t; r < TR; r += blockDim.x) {
        int e = g_eidx[r];
        int pos = soff[e] + atomicAdd(&scur[e], 1);
        g_row_map[pos]  = r >> 1;
        g_repl_map[pos] = r;
    }
}

// ============ GEMM1: CTA 128m x 32n, warp 32m x 16n over W1 & W3 ============
__global__ void __launch_bounds__(256, 2)
k_gemm1(const float* __restrict__ x,
        const float* __restrict__ w1,
        const float* __restrict__ w3, int c0) {
    extern __shared__ char smem[];
    int bx = blockIdx.x;
    if (bx >= g_ntiles) return;
    int e  = g_tile_e[bx];
    int r0 = g_tile_row[bx];
    int nl = blockIdx.y * 32;

    const float* W1 = w1 + (size_t)e * D_DIM * M_DIM + c0 + nl;
    const float* W3 = w3 + (size_t)e * D_DIM * M_DIM + c0 + nl;

    int tid = threadIdx.x;
    int w = tid >> 5, lane = tid & 31, g = lane >> 2, q = lane & 3;
    int m0 = (w & 3) * 32, n0w = (w >> 2) * 16;

    int k4 = tid & 7, mrow = tid >> 3;      // A loader
    int bn = tid & 31, kg = tid >> 5;       // B loader

    const float* aptr[4];
#pragma unroll
    for (int i = 0; i < 4; i++) {
        int gr = g_row_map[r0 + mrow + 32 * i];
        aptr[i] = (gr >= 0) ? x + (size_t)gr * D_DIM : (const float*)0;
    }

    char* buf[2] = { smem, smem + STG_BYTES };
    float c1[2][2][4] = {{{0}}}, c3[2][2][4] = {{{0}}};

    float4 va[4]; float2 vb1[2], vb3[2];
#pragma unroll
    for (int i = 0; i < 4; i++)
        va[i] = aptr[i] ? *(const float4*)(aptr[i] + k4 * 4) : make_float4(0.f,0.f,0.f,0.f);
#pragma unroll
    for (int j = 0; j < 2; j++) {
        int kk = (kg * 2 + j) * 2;
        vb1[j] = make_float2(W1[(size_t)kk * M_DIM + bn], W1[(size_t)(kk + 1) * M_DIM + bn]);
        vb3[j] = make_float2(W3[(size_t)kk * M_DIM + bn], W3[(size_t)(kk + 1) * M_DIM + bn]);
    }
    {
        char* s = buf[0];
        uint32_t ao = (uint32_t)mrow * PITCH + k4 * 8;
        *(uint2*)(s + OFF_AH + ao) = make_uint2(phi(va[0].x, va[0].y), phi(va[0].z, va[0].w));
        *(uint2*)(s + OFF_AL + ao) = make_uint2(plo(va[0].x, va[0].y), plo(va[0].z, va[0].w));
#pragma unroll
        for (int i = 1; i < 4; i++) {
            uint32_t o = ao + i * 32 * PITCH;
            *(uint2*)(s + OFF_AH + o) = make_uint2(phi(va[i].x, va[i].y), phi(va[i].z, va[i].w));
            *(uint2*)(s + OFF_AL + o) = make_uint2(plo(va[i].x, va[i].y), plo(va[i].z, va[i].w));
        }
        uint32_t bo = (uint32_t)bn * PITCH + kg * 8;
        *(uint2*)(s + G1_B1H + bo) = make_uint2(phi(vb1[0].x, vb1[0].y), phi(vb1[1].x, vb1[1].y));
        *(uint2*)(s + G1_B1L + bo) = make_uint2(plo(vb1[0].x, vb1[0].y), plo(vb1[1].x, vb1[1].y));
        *(uint2*)(s + G1_B3H + bo) = make_uint2(phi(vb3[0].x, vb3[0].y), phi(vb3[1].x, vb3[1].y));
        *(uint2*)(s + G1_B3L + bo) = make_uint2(plo(vb3[0].x, vb3[0].y), plo(vb3[1].x, vb3[1].y));
    }
    __syncthreads();

    const int NIT = D_DIM / BK;   // 64
    for (int it = 0; it < NIT; it++) {
        bool pf = (it + 1 < NIT);
        int nk0 = (it + 1) * BK;
        if (pf) {
#pragma unroll
            for (int i = 0; i < 4; i++)
                va[i] = aptr[i] ? *(const float4*)(aptr[i] + nk0 + k4 * 4) : make_float4(0.f,0.f,0.f,0.f);
#pragma unroll
            for (int j = 0; j < 2; j++) {
                int kk = nk0 + (kg * 2 + j) * 2;
                vb1[j] = make_float2(W1[(size_t)kk * M_DIM + bn], W1[(size_t)(kk + 1) * M_DIM + bn]);
                vb3[j] = make_float2(W3[(size_t)kk * M_DIM + bn], W3[(size_t)(kk + 1) * M_DIM + bn]);
            }
        }
        {
            const char* s = buf[it & 1];
#pragma unroll
            for (int ks = 0; ks < 2; ks++) {
                uint32_t aH[2][4], aL[2][4];
#pragma unroll
                for (int mi = 0; mi < 2; mi++) {
                    uint32_t o = (uint32_t)(m0 + mi * 16 + g) * PITCH + ks * 32 + q * 4;
                    aH[mi][0] = lds32(s + OFF_AH + o);
                    aH[mi][1] = lds32(s + OFF_AH + o + 8 * PITCH);
                    aH[mi][2] = lds32(s + OFF_AH + o + 16);
                    aH[mi][3] = lds32(s + OFF_AH + o + 8 * PITCH + 16);
                    aL[mi][0] = lds32(s + OFF_AL + o);
                    aL[mi][1] = lds32(s + OFF_AL + o + 8 * PITCH);
                    aL[mi][2] = lds32(s + OFF_AL + o + 16);
                    aL[mi][3] = lds32(s + OFF_AL + o + 8 * PITCH + 16);
                }
                uint32_t bh[2][2], bl[2][2];
#pragma unroll
                for (int ni = 0; ni < 2; ni++) {
                    uint32_t o = (uint32_t)(n0w + ni * 8 + g) * PITCH + ks * 32 + q * 4;
                    bh[ni][0] = lds32(s + G1_B1H + o);
                    bh[ni][1] = lds32(s + G1_B1H + o + 16);
                    bl[ni][0] = lds32(s + G1_B1L + o);
                    bl[ni][1] = lds32(s + G1_B1L + o + 16);
                }
#pragma unroll
                for (int mi = 0; mi < 2; mi++)
#pragma unroll
                    for (int ni = 0; ni < 2; ni++) {
                        mma16816(c1[mi][ni], aH[mi], bh[ni]);
                        mma16816(c1[mi][ni], aL[mi], bh[ni]);
                        mma16816(c1[mi][ni], aH[mi], bl[ni]);
                    }
#pragma unroll
                for (int ni = 0; ni < 2; ni++) {
                    uint32_t o = (uint32_t)(n0w + ni * 8 + g) * PITCH + ks * 32 + q * 4;
                    bh[ni][0] = lds32(s + G1_B3H + o);
                    bh[ni][1] = lds32(s + G1_B3H + o + 16);
                    bl[ni][0] = lds32(s + G1_B3L + o);
                    bl[ni][1] = lds32(s + G1_B3L + o + 16);
                }
#pragma unroll
                for (int mi = 0; mi < 2; mi++)
#pragma unroll
                    for (int ni = 0; ni < 2; ni++) {
                        mma16816(c3[mi][ni], aH[mi], bh[ni]);
                        mma16816(c3[mi][ni], aL[mi], bh[ni]);
                        mma16816(c3[mi][ni], aH[mi], bl[ni]);
                    }
            }
        }
        if (pf) {
            char* s = buf[(it + 1) & 1];
            uint32_t ao = (uint32_t)mrow * PITCH + k4 * 8;
#pragma unroll
            for (int i = 0; i < 4; i++) {
                uint32_t o = ao + i * 32 * PITCH;
                *(uint2*)(s + OFF_AH + o) = make_uint2(phi(va[i].x, va[i].y), phi(va[i].z, va[i].w));
                *(uint2*)(s + OFF_AL + o) = make_uint2(plo(va[i].x, va[i].y), plo(va[i].z, va[i].w));
            }
            uint32_t bo = (uint32_t)bn * PITCH + kg * 8;
            *(uint2*)(s + G1_B1H + bo) = make_uint2(phi(vb1[0].x, vb1[0].y), phi(vb1[1].x, vb1[1].y));
            *(uint2*)(s + G1_B1L + bo) = make_uint2(plo(vb1[0].x, vb1[0].y), plo(vb1[1].x, vb1[1].y));
            *(uint2*)(s + G1_B3H + bo) = make_uint2(phi(vb3[0].x, vb3[0].y), phi(vb3[1].x, vb3[1].y));
            *(uint2*)(s + G1_B3L + bo) = make_uint2(plo(vb3[0].x, vb3[0].y), plo(vb3[1].x, vb3[1].y));
        }
        __syncthreads();
    }

    // epilogue
#pragma unroll
    for (int mi = 0; mi < 2; mi++)
#pragma unroll
        for (int ni = 0; ni < 2; ni++) {
            int rt = m0 + mi * 16 + g;
            int cb = nl + n0w + ni * 8 + q * 2;
            float* p0 = g_hc + (size_t)(r0 + rt) * CHUNK_M + cb;
            float2 o0;
            o0.x = silu(c1[mi][ni][0]) * c3[mi][ni][0];
            o0.y = silu(c1[mi][ni][1]) * c3[mi][ni][1];
            *(float2*)p0 = o0;
            float* p1 = g_hc + (size_t)(r0 + rt + 8) * CHUNK_M + cb;
            float2 o1;
            o1.x = silu(c1[mi][ni][2]) * c3[mi][ni][2];
            o1.y = silu(c1[mi][ni][3]) * c3[mi][ni][3];
            *(float2*)p1 = o1;
        }
}

// ============ GEMM2: CTA 128m x 64n, warp 32m x 32n ============
__global__ void __launch_bounds__(256, 2)
k_gemm2(const float* __restrict__ w2, int c0, int first) {
    extern __shared__ char smem[];
    int bx = blockIdx.x;
    if (bx >= g_ntiles) return;
    int e  = g_tile_e[bx];
    int r0 = g_tile_row[bx];
    int n0 = blockIdx.y * 64;

    const float* W2 = w2 + (size_t)e * M_DIM * D_DIM + (size_t)c0 * D_DIM + n0;

    int tid = threadIdx.x;
    int w = tid >> 5, lane = tid & 31, g = lane >> 2, q = lane & 3;
    int m0 = (w & 3) * 32, n0w = (w >> 2) * 32;

    int k4 = tid & 7, mrow = tid >> 3;
    int bn = tid & 63, kg = tid >> 6;       // kg 0..3, 4 k-pairs each

    const float* aptr[4];
#pragma unroll
    for (int i = 0; i < 4; i++)
        aptr[i] = g_hc + (size_t)(r0 + mrow + 32 * i) * CHUNK_M;

    char* buf[2] = { smem, smem + STG_BYTES };
    float c[2][4][4] = {{{0}}};

    float4 va[4]; float2 vb[4];
#pragma unroll
    for (int i = 0; i < 4; i++) va[i] = *(const float4*)(aptr[i] + k4 * 4);
#pragma unroll
    for (int j = 0; j < 4; j++) {
        int kk = (kg * 4 + j) * 2;
        vb[j] = make_float2(W2[(size_t)kk * D_DIM + bn], W2[(size_t)(kk + 1) * D_DIM + bn]);
    }
    {
        char* s = buf[0];
        uint32_t ao = (uint32_t)mrow * PITCH + k4 * 8;
#pragma unroll
        for (int i = 0; i < 4; i++) {
            uint32_t o = ao + i * 32 * PITCH;
            *(uint2*)(s + OFF_AH + o) = make_uint2(phi(va[i].x, va[i].y), phi(va[i].z, va[i].w));
            *(uint2*)(s + OFF_AL + o) = make_uint2(plo(va[i].x, va[i].y), plo(va[i].z, va[i].w));
        }
        uint32_t bo = (uint32_t)bn * PITCH + kg * 16;
        *(uint4*)(s + G2_BH + bo) = make_uint4(phi(vb[0].x, vb[0].y), phi(vb[1].x, vb[1].y),
                                               phi(vb[2].x, vb[2].y), phi(vb[3].x, vb[3].y));
        *(uint4*)(s + G2_BL + bo) = make_uint4(plo(vb[0].x, vb[0].y), plo(vb[1].x, vb[1].y),
                                               plo(vb[2].x, vb[2].y), plo(vb[3].x, vb[3].y));
    }
    __syncthreads();

    const int NIT = CHUNK_M / BK;  // 56
    for (int it = 0; it < NIT; it++) {
        bool pf = (it + 1 < NIT);
        int nk0 = (it + 1) * BK;
        if (pf) {
#pragma unroll
            for (int i = 0; i < 4; i++) va[i] = *(const float4*)(aptr[i] + nk0 + k4 * 4);
#pragma unroll
            for (int j = 0; j < 4; j++) {
                int kk = nk0 + (kg * 4 + j) * 2;
                vb[j] = make_float2(W2[(size_t)kk * D_DIM + bn], W2[(size_t)(kk + 1) * D_DIM + bn]);
            }
        }
        {
            const char* s = buf[it & 1];
#pragma unroll
            for (int ks = 0; ks < 2; ks++) {
                uint32_t aH[2][4], aL[2][4];
#pragma unroll
                for (int mi = 0; mi < 2; mi++) {
                    uint32_t o = (uint32_t)(m0 + mi * 16 + g) * PITCH + ks * 32 + q * 4;
                    aH[mi][0] = lds32(s + OFF_AH + o);
                    aH[mi][1] = lds32(s + OFF_AH + o + 8 * PITCH);
                    aH[mi][2] = lds32(s + OFF_AH + o + 16);
                    aH[mi][3] = lds32(s + OFF_AH + o + 8 * PITCH + 16);
                    aL[mi][0] = lds32(s + OFF_AL + o);
                    aL[mi][1] = lds32(s + OFF_AL + o + 8 * PITCH);
                    aL[mi][2] = lds32(s + OFF_AL + o + 16);
                    aL[mi][3] = lds32(s + OFF_AL + o + 8 * PITCH + 16);
                }
#pragma unroll
                for (int ni = 0; ni < 4; ni++) {
                    uint32_t o = (uint32_t)(n0w + ni * 8 + g) * PITCH + ks * 32 + q * 4;
                    uint32_t bHf[2], bLf[2];
                    bHf[0] = lds32(s + G2_BH + o);
                    bHf[1] = lds32(s + G2_BH + o + 16);
                    bLf[0] = lds32(s + G2_BL + o);
                    bLf[1] = lds32(s + G2_BL + o + 16);
#pragma unroll
                    for (int mi = 0; mi < 2; mi++) {
                        mma16816(c[mi][ni], aH[mi], bHf);
                        mma16816(c[mi][ni], aL[mi], bHf);
                        mma16816(c[mi][ni], aH[mi], bLf);
                    }
                }
            }
        }
        if (pf) {
            char* s = buf[(it + 1) & 1];
            uint32_t ao = (uint32_t)mrow * PITCH + k4 * 8;
#pragma unroll
            for (int i = 0; i < 4; i++) {
                uint32_t o = ao + i * 32 * PITCH;
                *(uint2*)(s + OFF_AH + o) = make_uint2(phi(va[i].x, va[i].y), phi(va[i].z, va[i].w));
                *(uint2*)(s + OFF_AL + o) = make_uint2(plo(va[i].x, va[i].y), plo(va[i].z, va[i].w));
            }
            uint32_t bo = (uint32_t)bn * PITCH + kg * 16;
            *(uint4*)(s + G2_BH + bo) = make_uint4(phi(vb[0].x, vb[0].y), phi(vb[1].x, vb[1].y),
                                                   phi(vb[2].x, vb[2].y), phi(vb[3].x, vb[3].y));
            *(uint4*)(s + G2_BL + bo) = make_uint4(plo(vb[0].x, vb[0].y), plo(vb[1].x, vb[1].y),
                                                   plo(vb[2].x, vb[2].y), plo(vb[3].x, vb[3].y));
        }
        __syncthreads();
    }

    // epilogue: accumulate into g_outrep, scatter by replica
#pragma unroll
    for (int mi = 0; mi < 2; mi++) {
        int rt = m0 + mi * 16 + g;
#pragma unroll
        for (int half = 0; half < 2; half++) {
            int row = rt + half * 8;
            int repl = g_repl_map[r0 + row];
            if (repl < 0) continue;
#pragma unroll
            for (int ni = 0; ni < 4; ni++) {
                int cb = n0 + n0w + ni * 8 + q * 2;
                float* p = g_outrep + (size_t)repl * D_DIM + cb;
                float2 v;
                v.x = c[mi][ni][half * 2 + 0];
                v.y = c[mi][ni][half * 2 + 1];
                if (!first) {
                    float2 old = *(const float2*)p;
                    v.x += old.x; v.y += old.y;
                }
                *(float2*)p = v;
            }
        }
    }
}

// ---------------- combine ----------------
__global__ void k_combine(float* __restrict__ out) {
    int i = blockIdx.x * blockDim.x + threadIdx.x;
    int t = i >> 9;
    int c = (i & 511) * 4;
    if (t >= T_TOK) return;
    float w0 = g_tw[2 * t], w1 = g_tw[2 * t + 1];
    float4 a = *(const float4*)&g_outrep[(size_t)(2 * t) * D_DIM + c];
    float4 b = *(const float4*)&g_outrep[(size_t)(2 * t + 1) * D_DIM + c];
    float4 o;
    o.x = w0 * a.x + w1 * b.x;
    o.y = w0 * a.y + w1 * b.y;
    o.z = w0 * a.z + w1 * b.z;
    o.w = w0 * a.w + w1 * b.w;
    *(float4*)&out[(size_t)t * D_DIM + c] = o;
}

// ---------------- launch ----------------
extern "C" void kernel_launch(void* const* d_in, const int* in_sizes, int n_in,
                              void* d_out, int out_size) {
    const float* x  = (const float*)d_in[0];
    const float* gw = (const float*)d_in[1];
    const float* w1 = (const float*)d_in[2];
    const float* w2 = (const float*)d_in[3];
    const float* w3 = (const float*)d_in[4];
    float* out = (float*)d_out;

    static int configured = 0;
    if (!configured) {
        cudaFuncSetAttribute(k_gemm1, cudaFuncAttributeMaxDynamicSharedMemorySize, SMEM_TOTAL);
        cudaFuncSetAttribute(k_gemm2, cudaFuncAttributeMaxDynamicSharedMemorySize, SMEM_TOTAL);
        configured = 1;
    }

    k_init<<<1, 256>>>();
    k_router<<<T_TOK / 8, 256>>>(x, gw);
    k_perm<<<1, 256>>>();
    for (int c = 0; c < N_CHUNKS; c++) {
        int c0 = c * CHUNK_M;
        k_gemm1<<<dim3(MAX_RT, CHUNK_M / 32), 256, SMEM_TOTAL>>>(x, w1, w3, c0);
        k_gemm2<<<dim3(MAX_RT, D_DIM / 64), 256, SMEM_TOTAL>>>(w2, c0, c == 0);
    }
    k_combine<<<(T_TOK * D_DIM / 4) / 256, 256>>>(out);
}